// round 10
// baseline (speedup 1.0000x reference)
#include <cuda_runtime.h>
#include <math.h>

#define B_   8
#define T_   2048
#define CH_  48
#define NH_  36
#define H_   12
#define W_   18
#define L_   512
#define R_   4
#define NW_  9
#define TT_  32

#define LATS_ELEMS (8ull*2048ull*18ull*512ull)
#define N0_ELEMS   (8ull*2048ull*16ull)
#define N1_ELEMS   (8ull*2048ull*64ull)
#define N2_ELEMS   (8ull*2048ull*256ull)
#define N3_ELEMS   (8ull*2048ull*1024ull)

#define STATS_BLOCKS 96
#define NBLK0 32
#define NBLK1 128
#define NBLK2 512
#define NBLK3 2048
#define NOISE_BLOCKS (NBLK0+NBLK1+NBLK2+NBLK3)   // 2720
#define LATS_BLOCKS  ((T_/TT_)*B_)               // 4096
#define TOTAL_BLOCKS (STATS_BLOCKS+NOISE_BLOCKS+LATS_BLOCKS)

__device__ float g_means[B_ * CH_];
__device__ float g_w[B_ * 4 * NW_];
__device__ int   g_ready;

// ---------------- f32x2 helpers ----------------
__device__ __forceinline__ unsigned long long pack2(float v) {
    unsigned long long r;
    asm("mov.b64 %0, {%1, %1};" : "=l"(r) : "f"(v));
    return r;
}
__device__ __forceinline__ unsigned long long packf2(float a, float b) {
    unsigned long long r;
    asm("mov.b64 %0, {%1, %2};" : "=l"(r) : "f"(a), "f"(b));
    return r;
}
__device__ __forceinline__ void unpack2(unsigned long long p, float& a, float& b) {
    asm("mov.b64 {%0, %1}, %2;" : "=f"(a), "=f"(b) : "l"(p));
}
__device__ __forceinline__ void fma2(unsigned long long& d,
                                     unsigned long long a,
                                     unsigned long long b) {
    asm("fma.rn.f32x2 %0, %1, %2, %0;" : "+l"(d) : "l"(a), "l"(b));
}

__device__ __forceinline__ int reflect_t(int t) {
    t = (t < 0) ? -t : t;
    return (t >= T_) ? (2 * T_ - 2 - t) : t;
}

// ---------------- reset flag ----------------
__global__ void k_reset() { g_ready = 0; }

// ---------------- stats path: one block per (b, c4) ----------------
__device__ __forceinline__ void stats_path(const float* __restrict__ x,
                                           void* s_buf, int sb) {
    int b  = sb / 12;
    int c4 = sb % 12;
    int tid = threadIdx.x;

    const float4* x4 = (const float4*)x;
    float4 acc = make_float4(0.f, 0.f, 0.f, 0.f);
#pragma unroll
    for (int it = 0; it < 8; it++) {
        float4 v = __ldg(&x4[(size_t)(b * T_ + it * 256 + tid) * 12 + c4]);
        acc.x += v.x; acc.y += v.y; acc.z += v.z; acc.w += v.w;
    }

    float4* sh4 = (float4*)s_buf;
    sh4[tid] = acc;
    __syncthreads();
    for (int o = 128; o > 0; o >>= 1) {
        if (tid < o) {
            float4 u = sh4[tid], v = sh4[tid + o];
            u.x += v.x; u.y += v.y; u.z += v.z; u.w += v.w;
            sh4[tid] = u;
        }
        __syncthreads();
    }

    if (tid == 0) {
        float4 s = sh4[0];
        float mv[4] = {s.x * (1.0f / T_), s.y * (1.0f / T_),
                       s.z * (1.0f / T_), s.w * (1.0f / T_)};
#pragma unroll
        for (int comp = 0; comp < 4; comp++) {
            int ch = c4 * 4 + comp;
            g_means[b * CH_ + ch] = mv[comp];
            int cc = ch - NH_;
            if (cc >= 0 && (cc % 3) == 2) {
                int i = cc / 3;
                float sig = fmaxf(mv[comp], 0.001f);
                float inv = -0.5f / (sig * sig);
                float ws[NW_];
                float sum = 0.f;
#pragma unroll
                for (int j = 0; j < NW_; j++) {
                    float k = (float)(j - R_);
                    ws[j] = expf(k * k * inv);
                    sum += ws[j];
                }
                float rs = 1.0f / sum;
#pragma unroll
                for (int j = 0; j < NW_; j++)
                    g_w[(b * 4 + i) * NW_ + j] = ws[j] * rs;
            }
        }
        __threadfence();           // producer side: push data to L2 before flag
        atomicAdd(&g_ready, 1);
    }
}

// ---------------- noise path (float4 columns, rolling 9-window) ----------------
__device__ __forceinline__ void noise_path(const float* __restrict__ x,
                                           const float* __restrict__ eps,
                                           float* __restrict__ out,
                                           int i, int nf4, int nb) {
    int idx = nb * 256 + threadIdx.x;
    int c = idx % nf4;
    int r = (idx / nf4) % (T_ / 8);
    int b = idx / (nf4 * (T_ / 8));
    int t0 = r * 8;

    float w[NW_];
#pragma unroll
    for (int j = 0; j < NW_; j++) w[j] = __ldcg(&g_w[(b * 4 + i) * NW_ + j]);

    int much  = NH_ + 3 * i;
    int sigch = much + 1;

    const float4* ep = (const float4*)eps;
    float4* op = (float4*)out + (size_t)(b * T_ + t0) * nf4 + c;

    float4 e[NW_];
    float  s[NW_], m[NW_];
#pragma unroll
    for (int k = 0; k < NW_; k++) {
        int tt = reflect_t(t0 - R_ + k);
        const float* xr = &x[(b * T_ + tt) * CH_];
        m[k] = xr[much];
        s[k] = xr[sigch];
        e[k] = __ldcs(&ep[(size_t)(b * T_ + tt) * nf4 + c]);
    }

#pragma unroll
    for (int u = 0; u < 8; u++) {
        float mu = 0.f;
        float4 a = make_float4(0.f, 0.f, 0.f, 0.f);
#pragma unroll
        for (int j = 0; j < NW_; j++) {
            int slot = (u + j) % NW_;
            mu += w[j] * m[slot];
            float cf = w[j] * s[slot];
            a.x = fmaf(cf, e[slot].x, a.x);
            a.y = fmaf(cf, e[slot].y, a.y);
            a.z = fmaf(cf, e[slot].z, a.z);
            a.w = fmaf(cf, e[slot].w, a.w);
        }
        a.x += mu; a.y += mu; a.z += mu; a.w += mu;
        __stcs(&op[(size_t)u * nf4], a);
        if (u < 7) {
            int tt = reflect_t(t0 + R_ + 1 + u);
            int slot = u % NW_;
            const float* xr = &x[(b * T_ + tt) * CH_];
            m[slot] = xr[much];
            s[slot] = xr[sigch];
            e[slot] = __ldcs(&ep[(size_t)(b * T_ + tt) * nf4 + c]);
        }
    }
}

// ---------------- lats path (float4 columns, TT_=32) ----------------
__device__ __forceinline__ void lats_path(const float* __restrict__ x,
                                          const float* __restrict__ table,
                                          float* __restrict__ out,
                                          unsigned long long* s_env, int lb) {
    int b  = lb / (T_ / TT_);
    int t0 = (lb % (T_ / TT_)) * TT_;

    for (int idx = threadIdx.x; idx < TT_ * NH_; idx += 256) {
        int t = idx / NH_;
        int c = idx % NH_;
        float v = x[(b * T_ + t0 + t) * CH_ + c] - __ldcg(&g_means[b * CH_ + c]);
        s_env[idx] = pack2(v);
    }
    __syncthreads();

    const float4* tab4 = (const float4*)table;
    float4* out4 = (float4*)out;
    size_t out_base = (size_t)(b * T_ + t0) * (W_ * L_ / 4);

#pragma unroll 1
    for (int k = 0; k < 9; k++) {
        int cidx = threadIdx.x + k * 256;
        int w = cidx >> 7;
        int g = w / 6;
        int lq = cidx & 127;

        unsigned long long tl[H_], th[H_];
        int tbase = (g * H_ * W_ + w) * (L_ / 4) + lq;
#pragma unroll
        for (int h = 0; h < H_; h++) {
            float4 tv = __ldg(&tab4[tbase + h * (W_ * L_ / 4)]);
            tl[h] = packf2(tv.x, tv.y);
            th[h] = packf2(tv.z, tv.w);
        }

        size_t obase = out_base + (size_t)w * (L_ / 4) + lq;
#pragma unroll
        for (int t = 0; t < TT_; t++) {
            unsigned long long a0 = 0ull, a1 = 0ull;
            const unsigned long long* ep2 = &s_env[t * NH_ + g * H_];
#pragma unroll
            for (int h = 0; h < H_; h++) {
                unsigned long long e = ep2[h];
                fma2(a0, e, tl[h]);
                fma2(a1, e, th[h]);
            }
            float4 rr;
            unpack2(a0, rr.x, rr.y);
            unpack2(a1, rr.z, rr.w);
            __stcs(&out4[obase + (size_t)t * (W_ * L_ / 4)], rr);
        }
    }
}

// ---------------- über-kernel ----------------
__global__ void __launch_bounds__(256, 3) k_uber(const float* __restrict__ x,
                                                 const float* __restrict__ table,
                                                 const float* __restrict__ eps0,
                                                 const float* __restrict__ eps1,
                                                 const float* __restrict__ eps2,
                                                 const float* __restrict__ eps3,
                                                 float* __restrict__ out) {
    __shared__ unsigned long long s_buf[TT_ * NH_];   // 9216B: stats float4[256] / lats env
    int bid = blockIdx.x;

    if (bid < STATS_BLOCKS) {
        stats_path(x, (void*)s_buf, bid);
        return;
    }

    // consumers: wait for stats. NO gpu-scope fence here (would CCTL.IVALL-flush
    // L1 in every block); params are read via __ldcg (L2), producer fenced.
    if (threadIdx.x == 0) {
        while (*(volatile int*)&g_ready != STATS_BLOCKS)
            __nanosleep(64);
    }
    __syncthreads();

    bid -= STATS_BLOCKS;
    if (bid < NOISE_BLOCKS) {
        if (bid < NBLK0) {
            noise_path(x, eps0, out + LATS_ELEMS, 0, 4, bid);
        } else if (bid < NBLK0 + NBLK1) {
            noise_path(x, eps1, out + LATS_ELEMS + N0_ELEMS, 1, 16, bid - NBLK0);
        } else if (bid < NBLK0 + NBLK1 + NBLK2) {
            noise_path(x, eps2, out + LATS_ELEMS + N0_ELEMS + N1_ELEMS, 2, 64,
                       bid - (NBLK0 + NBLK1));
        } else {
            noise_path(x, eps3, out + LATS_ELEMS + N0_ELEMS + N1_ELEMS + N2_ELEMS, 3, 256,
                       bid - (NBLK0 + NBLK1 + NBLK2));
        }
    } else {
        lats_path(x, table, out, s_buf, bid - NOISE_BLOCKS);
    }
}

extern "C" void kernel_launch(void* const* d_in, const int* in_sizes, int n_in,
                              void* d_out, int out_size) {
    const float* x     = (const float*)d_in[0];
    const float* table = (const float*)d_in[1];
    const float* eps0  = (const float*)d_in[2];
    const float* eps1  = (const float*)d_in[3];
    const float* eps2  = (const float*)d_in[4];
    const float* eps3  = (const float*)d_in[5];
    float* out = (float*)d_out;

    k_reset<<<1, 1>>>();
    k_uber<<<TOTAL_BLOCKS, 256>>>(x, table, eps0, eps1, eps2, eps3, out);
}

// round 11
// speedup vs baseline: 1.1027x; 1.1027x over previous
#include <cuda_runtime.h>
#include <math.h>

#define B_   8
#define T_   2048
#define CH_  48
#define NH_  36
#define H_   12
#define W_   18
#define L_   512
#define R_   4
#define NW_  9
#define TT_  16

#define LATS_ELEMS (8ull*2048ull*18ull*512ull)
#define N0_ELEMS   (8ull*2048ull*16ull)
#define N1_ELEMS   (8ull*2048ull*64ull)
#define N2_ELEMS   (8ull*2048ull*256ull)
#define N3_ELEMS   (8ull*2048ull*1024ull)

#define NBLK0 32
#define NBLK1 128
#define NBLK2 512
#define NBLK3 2048
#define NOISE_BLOCKS (NBLK0+NBLK1+NBLK2+NBLK3)   // 2720
#define LATS_BLOCKS  ((T_/TT_)*B_)               // 8192

__device__ float g_means[B_ * CH_];
__device__ float g_w[B_ * 4 * NW_];

// ---------------- f32x2 helpers ----------------
__device__ __forceinline__ unsigned long long pack2(float v) {
    unsigned long long r;
    asm("mov.b64 %0, {%1, %1};" : "=l"(r) : "f"(v));
    return r;
}
__device__ __forceinline__ unsigned long long packf2(float a, float b) {
    unsigned long long r;
    asm("mov.b64 %0, {%1, %2};" : "=l"(r) : "f"(a), "f"(b));
    return r;
}
__device__ __forceinline__ void unpack2(unsigned long long p, float& a, float& b) {
    asm("mov.b64 {%0, %1}, %2;" : "=f"(a), "=f"(b) : "l"(p));
}
__device__ __forceinline__ void fma2(unsigned long long& d,
                                     unsigned long long a,
                                     unsigned long long b) {
    asm("fma.rn.f32x2 %0, %1, %2, %0;" : "+l"(d) : "l"(a), "l"(b));
}

__device__ __forceinline__ int reflect_t(int t) {
    t = (t < 0) ? -t : t;
    return (t >= T_) ? (2 * T_ - 2 - t) : t;
}

// ---------------- stats: 96 blocks, one per (b, float4 column) ----------------
__global__ void __launch_bounds__(256) k_stats(const float* __restrict__ x) {
    int b  = blockIdx.x / 12;
    int c4 = blockIdx.x % 12;
    int tid = threadIdx.x;

    const float4* x4 = (const float4*)x;
    float4 acc = make_float4(0.f, 0.f, 0.f, 0.f);
#pragma unroll
    for (int it = 0; it < 8; it++) {
        float4 v = __ldg(&x4[(size_t)(b * T_ + it * 256 + tid) * 12 + c4]);
        acc.x += v.x; acc.y += v.y; acc.z += v.z; acc.w += v.w;
    }

    __shared__ float4 sh4[256];
    sh4[tid] = acc;
    __syncthreads();
    for (int o = 128; o > 0; o >>= 1) {
        if (tid < o) {
            float4 u = sh4[tid], v = sh4[tid + o];
            u.x += v.x; u.y += v.y; u.z += v.z; u.w += v.w;
            sh4[tid] = u;
        }
        __syncthreads();
    }

    if (tid == 0) {
        float4 s = sh4[0];
        float mv[4] = {s.x * (1.0f / T_), s.y * (1.0f / T_),
                       s.z * (1.0f / T_), s.w * (1.0f / T_)};
#pragma unroll
        for (int comp = 0; comp < 4; comp++) {
            int ch = c4 * 4 + comp;
            g_means[b * CH_ + ch] = mv[comp];
            int cc = ch - NH_;
            if (cc >= 0 && (cc % 3) == 2) {
                int i = cc / 3;
                float sig = fmaxf(mv[comp], 0.001f);
                float inv = -0.5f / (sig * sig);
                float ws[NW_];
                float sum = 0.f;
#pragma unroll
                for (int j = 0; j < NW_; j++) {
                    float k = (float)(j - R_);
                    ws[j] = expf(k * k * inv);
                    sum += ws[j];
                }
                float rs = 1.0f / sum;
#pragma unroll
                for (int j = 0; j < NW_; j++)
                    g_w[(b * 4 + i) * NW_ + j] = ws[j] * rs;
            }
        }
    }
}

// ---------------- noise path (float4 columns, rolling 9-window) ----------------
__device__ __forceinline__ void noise_path(const float* __restrict__ x,
                                           const float* __restrict__ eps,
                                           float* __restrict__ out,
                                           int i, int nf4, int nb) {
    int idx = nb * 256 + threadIdx.x;
    int c = idx % nf4;
    int r = (idx / nf4) % (T_ / 8);
    int b = idx / (nf4 * (T_ / 8));
    int t0 = r * 8;

    float w[NW_];
#pragma unroll
    for (int j = 0; j < NW_; j++) w[j] = g_w[(b * 4 + i) * NW_ + j];

    int much  = NH_ + 3 * i;
    int sigch = much + 1;

    const float4* ep = (const float4*)eps;
    float4* op = (float4*)out + (size_t)(b * T_ + t0) * nf4 + c;

    float4 e[NW_];
    float  s[NW_], m[NW_];
#pragma unroll
    for (int k = 0; k < NW_; k++) {
        int tt = reflect_t(t0 - R_ + k);
        const float* xr = &x[(b * T_ + tt) * CH_];
        m[k] = xr[much];
        s[k] = xr[sigch];
        e[k] = __ldcs(&ep[(size_t)(b * T_ + tt) * nf4 + c]);
    }

#pragma unroll
    for (int u = 0; u < 8; u++) {
        float mu = 0.f;
        float4 a = make_float4(0.f, 0.f, 0.f, 0.f);
#pragma unroll
        for (int j = 0; j < NW_; j++) {
            int slot = (u + j) % NW_;
            mu += w[j] * m[slot];
            float cf = w[j] * s[slot];
            a.x = fmaf(cf, e[slot].x, a.x);
            a.y = fmaf(cf, e[slot].y, a.y);
            a.z = fmaf(cf, e[slot].z, a.z);
            a.w = fmaf(cf, e[slot].w, a.w);
        }
        a.x += mu; a.y += mu; a.z += mu; a.w += mu;
        __stcs(&op[(size_t)u * nf4], a);
        if (u < 7) {
            int tt = reflect_t(t0 + R_ + 1 + u);
            int slot = u % NW_;
            const float* xr = &x[(b * T_ + tt) * CH_];
            m[slot] = xr[much];
            s[slot] = xr[sigch];
            e[slot] = __ldcs(&ep[(size_t)(b * T_ + tt) * nf4 + c]);
        }
    }
}

// ---------------- lats path (float4 columns, TT_=16) ----------------
__device__ __forceinline__ void lats_path(const float* __restrict__ x,
                                          const float* __restrict__ table,
                                          float* __restrict__ out,
                                          int lb) {
    int b  = lb / (T_ / TT_);
    int t0 = (lb % (T_ / TT_)) * TT_;

    __shared__ unsigned long long s_env[TT_ * NH_];
    for (int idx = threadIdx.x; idx < TT_ * NH_; idx += 256) {
        int t = idx / NH_;
        int c = idx % NH_;
        float v = x[(b * T_ + t0 + t) * CH_ + c] - g_means[b * CH_ + c];
        s_env[idx] = pack2(v);
    }
    __syncthreads();

    const float4* tab4 = (const float4*)table;
    float4* out4 = (float4*)out;
    size_t out_base = (size_t)(b * T_ + t0) * (W_ * L_ / 4);

#pragma unroll 1
    for (int k = 0; k < 9; k++) {
        int cidx = threadIdx.x + k * 256;
        int w = cidx >> 7;
        int g = w / 6;
        int lq = cidx & 127;

        unsigned long long tl[H_], th[H_];
        int tbase = (g * H_ * W_ + w) * (L_ / 4) + lq;
#pragma unroll
        for (int h = 0; h < H_; h++) {
            float4 tv = __ldg(&tab4[tbase + h * (W_ * L_ / 4)]);
            tl[h] = packf2(tv.x, tv.y);
            th[h] = packf2(tv.z, tv.w);
        }

        size_t obase = out_base + (size_t)w * (L_ / 4) + lq;
#pragma unroll
        for (int t = 0; t < TT_; t++) {
            unsigned long long a0 = 0ull, a1 = 0ull;
            const unsigned long long* ep2 = &s_env[t * NH_ + g * H_];
#pragma unroll
            for (int h = 0; h < H_; h++) {
                unsigned long long e = ep2[h];
                fma2(a0, e, tl[h]);
                fma2(a1, e, th[h]);
            }
            float4 rr;
            unpack2(a0, rr.x, rr.y);
            unpack2(a1, rr.z, rr.w);
            __stcs(&out4[obase + (size_t)t * (W_ * L_ / 4)], rr);
        }
    }
}

// ---------------- über-kernel ----------------
__global__ void __launch_bounds__(256, 3) k_uber(const float* __restrict__ x,
                                                 const float* __restrict__ table,
                                                 const float* __restrict__ eps0,
                                                 const float* __restrict__ eps1,
                                                 const float* __restrict__ eps2,
                                                 const float* __restrict__ eps3,
                                                 float* __restrict__ out) {
    int bid = blockIdx.x;
    if (bid < NOISE_BLOCKS) {
        if (bid < NBLK0) {
            noise_path(x, eps0, out + LATS_ELEMS, 0, 4, bid);
        } else if (bid < NBLK0 + NBLK1) {
            noise_path(x, eps1, out + LATS_ELEMS + N0_ELEMS, 1, 16, bid - NBLK0);
        } else if (bid < NBLK0 + NBLK1 + NBLK2) {
            noise_path(x, eps2, out + LATS_ELEMS + N0_ELEMS + N1_ELEMS, 2, 64,
                       bid - (NBLK0 + NBLK1));
        } else {
            noise_path(x, eps3, out + LATS_ELEMS + N0_ELEMS + N1_ELEMS + N2_ELEMS, 3, 256,
                       bid - (NBLK0 + NBLK1 + NBLK2));
        }
    } else {
        lats_path(x, table, out, bid - NOISE_BLOCKS);
    }
}

extern "C" void kernel_launch(void* const* d_in, const int* in_sizes, int n_in,
                              void* d_out, int out_size) {
    const float* x     = (const float*)d_in[0];
    const float* table = (const float*)d_in[1];
    const float* eps0  = (const float*)d_in[2];
    const float* eps1  = (const float*)d_in[3];
    const float* eps2  = (const float*)d_in[4];
    const float* eps3  = (const float*)d_in[5];
    float* out = (float*)d_out;

    k_stats<<<96, 256>>>(x);
    k_uber<<<NOISE_BLOCKS + LATS_BLOCKS, 256>>>(x, table, eps0, eps1, eps2, eps3, out);
}